// round 13
// baseline (speedup 1.0000x reference)
#include <cuda_runtime.h>
#include <math.h>

#define T_ 256
#define B_ 256
#define C_ 64
#define H_ 512
#define G_ 2048
#define K_ 640   // 512 (h) + 64 (c_c) + 64 (m)
#define NBLK 128
#define NTHR 512

// ---- static device scratch ----
__device__ float g_v[T_*B_*C_];
__device__ float g_m[T_*B_*C_];
__device__ float g_d[T_*B_*C_];
__device__ float g_gh[T_*B_*H_];    // gamma_h (134MB)
__device__ float g_al[T_*B_*C_];
__device__ float g_A[B_*128];       // [c_c | m] (h part staged from g_h*g_gh)
__device__ float g_h[B_*H_];
__device__ float g_Wcat[G_*K_];     // [u*4+gate][k]
__device__ float g_bias[G_];
__device__ float g_WhT[H_*C_];
__device__ float g_WfT[C_*C_];
__device__ float g_WcT[2*C_*C_];
__device__ float g_diag[C_];
__device__ unsigned g_arrive;
__device__ unsigned g_gen;

// ---- f32x2 packed FMA helpers ----
__device__ __forceinline__ unsigned long long dup2(float a) {
    unsigned long long r;
    asm("mov.b64 %0, {%1,%1};" : "=l"(r) : "f"(a));
    return r;
}
__device__ __forceinline__ void ffma2(unsigned long long& d, unsigned long long a,
                                      unsigned long long b) {
    asm("fma.rn.f32x2 %0, %1, %2, %0;" : "+l"(d) : "l"(a), "l"(b));
}
__device__ __forceinline__ float2 upk2(unsigned long long v) {
    float2 f;
    asm("mov.b64 {%0,%1}, %2;" : "=f"(f.x), "=f"(f.y) : "l"(v));
    return f;
}

// ---- grid barrier (proven version) ----
__device__ __forceinline__ void gbar() {
    __threadfence();
    __syncthreads();
    if (threadIdx.x == 0) {
        unsigned gen;
        asm volatile("ld.acquire.gpu.global.u32 %0, [%1];" : "=r"(gen) : "l"(&g_gen));
        unsigned a = atomicAdd(&g_arrive, 1u);
        if (a == NBLK - 1) {
            atomicExch(&g_arrive, 0u);
            __threadfence();
            atomicAdd(&g_gen, 1u);
        } else {
            unsigned g;
            do {
                __nanosleep(64);
                asm volatile("ld.acquire.gpu.global.u32 %0, [%1];" : "=r"(g) : "l"(&g_gen));
            } while (g == gen);
        }
    }
    __syncthreads();
}

// ======================= preamble kernels (3 launches) =======================

__global__ void k_pack(const float* __restrict__ Wih,   const float* __restrict__ Whh,
                       const float* __restrict__ Whist, const float* __restrict__ Wfeat,
                       const float* __restrict__ Wcomb, const float* __restrict__ bih,
                       const float* __restrict__ bhh,   const float* __restrict__ Wgx) {
    int tid = blockIdx.x*blockDim.x + threadIdx.x, n = gridDim.x*blockDim.x;
    for (int i = tid; i < G_*K_; i += n) {
        int gp = i / K_, k = i % K_;
        int u = gp >> 2, gate = gp & 3;
        int go = gate*H_ + u;
        float w;
        if (k < H_)            w = Whh[go*H_ + k];
        else if (k < H_ + C_)  w = Wih[go*2*C_ + (k - H_)];
        else                   w = Wih[go*2*C_ + C_ + (k - H_ - C_)];
        g_Wcat[i] = w;
    }
    for (int i = tid; i < H_*C_; i += n) { int u=i/C_, c=i%C_; g_WhT[i] = Whist[c*H_ + u]; }
    for (int i = tid; i < C_*C_; i += n) { int j=i/C_, c=i%C_; g_WfT[i] = (j==c)?0.f:Wfeat[c*C_ + j]; }
    for (int i = tid; i < 2*C_*C_; i += n) { int j=i/C_, c=i%C_; g_WcT[i] = Wcomb[c*2*C_ + j]; }
    for (int i = tid; i < C_; i += n) g_diag[i] = Wgx[i*C_ + i];
    for (int i = tid; i < G_; i += n) { int u=i>>2, g=i&3; int go=g*H_+u; g_bias[i] = bih[go] + bhh[go]; }
    for (int i = tid; i < B_*H_; i += n) g_h[i] = 0.f;
}

__global__ void k_prep(const float* __restrict__ data) {
    int id = blockIdx.x*blockDim.x + threadIdx.x;
    if (id >= B_*C_) return;
    int b = id / C_, c = id % C_;
    float dec = 1.f, m_prev = 1.f;
    for (int t = 0; t < T_; t++) {
        float x = data[(b*T_ + t)*C_ + c];
        float m = (x != x) ? 0.f : 1.f;
        float v = (x != x) ? 0.f : x;
        float del;
        if (t == 0) del = 0.f;
        else if (t == 1) del = 1.f;
        else { dec = (m_prev == 1.f) ? 1.f : dec + 1.f; del = dec; }
        int o = (t*B_ + b)*C_ + c;
        g_v[o] = v; g_m[o] = m; g_d[o] = del;
        m_prev = m;
    }
}

__global__ void __launch_bounds__(256) k_ga(const float* __restrict__ Wgh,
                                            const float* __restrict__ bgh,
                                            const float* __restrict__ bgx,
                                            const float* __restrict__ bcomb) {
    __shared__ __align__(16) float As[2][32][68];
    __shared__ __align__(16) float Ws[2][32][68];
    __shared__ float gx[4][C_], ms[4][C_];
    int m0 = (blockIdx.x >> 3) << 6;
    int n0 = (blockIdx.x & 7) << 6;
    int tid = threadIdx.x, tx = tid & 15, ty = tid >> 4;
    int mm = tid >> 3, kk4 = (tid & 7) << 2;

    unsigned long long acc[4][2] = {};
    #define STAGE_G(buf, kc) { \
        float4 a0 = *(const float4*)&g_d[(m0+mm)*C_ + (kc) + kk4]; \
        float4 a1 = *(const float4*)&g_d[(m0+mm+32)*C_ + (kc) + kk4]; \
        float4 w0 = *(const float4*)&Wgh[(n0+mm)*C_ + (kc) + kk4]; \
        float4 w1 = *(const float4*)&Wgh[(n0+mm+32)*C_ + (kc) + kk4]; \
        As[buf][kk4+0][mm]=a0.x; As[buf][kk4+1][mm]=a0.y; As[buf][kk4+2][mm]=a0.z; As[buf][kk4+3][mm]=a0.w; \
        As[buf][kk4+0][mm+32]=a1.x; As[buf][kk4+1][mm+32]=a1.y; As[buf][kk4+2][mm+32]=a1.z; As[buf][kk4+3][mm+32]=a1.w; \
        Ws[buf][kk4+0][mm]=w0.x; Ws[buf][kk4+1][mm]=w0.y; Ws[buf][kk4+2][mm]=w0.z; Ws[buf][kk4+3][mm]=w0.w; \
        Ws[buf][kk4+0][mm+32]=w1.x; Ws[buf][kk4+1][mm+32]=w1.y; Ws[buf][kk4+2][mm+32]=w1.z; Ws[buf][kk4+3][mm+32]=w1.w; }

    STAGE_G(0, 0);
    __syncthreads();
    #pragma unroll
    for (int ch = 0; ch < 2; ch++) {
        int buf = ch & 1;
        if (ch < 1) STAGE_G(1, 32);
        #pragma unroll
        for (int kk = 0; kk < 32; kk++) {
            float4 a = *(const float4*)&As[buf][kk][tx*4];
            ulonglong2 w = *(const ulonglong2*)&Ws[buf][kk][ty*4];
            unsigned long long a0 = dup2(a.x), a1 = dup2(a.y), a2 = dup2(a.z), a3 = dup2(a.w);
            ffma2(acc[0][0], a0, w.x); ffma2(acc[0][1], a0, w.y);
            ffma2(acc[1][0], a1, w.x); ffma2(acc[1][1], a1, w.y);
            ffma2(acc[2][0], a2, w.x); ffma2(acc[2][1], a2, w.y);
            ffma2(acc[3][0], a3, w.x); ffma2(acc[3][1], a3, w.y);
        }
        __syncthreads();
    }
    int u0 = n0 + ty*4;
    float4 b4 = *(const float4*)&bgh[u0];
    #pragma unroll
    for (int mi = 0; mi < 4; mi++) {
        int row = m0 + tx*4 + mi;
        float2 p0 = upk2(acc[mi][0]), p1 = upk2(acc[mi][1]);
        float4 v;
        v.x = expf(-fmaxf(p0.x + b4.x, 0.f));
        v.y = expf(-fmaxf(p0.y + b4.y, 0.f));
        v.z = expf(-fmaxf(p1.x + b4.z, 0.f));
        v.w = expf(-fmaxf(p1.y + b4.w, 0.f));
        *(float4*)&g_gh[row*H_ + u0] = v;
    }
    #undef STAGE_G

    __syncthreads();
    int row0 = blockIdx.x * 8;
    int r = tid >> 6, i = tid & 63;
    for (int p = 0; p < 2; p++) {
        int row = row0 + p*4 + r;
        float d = g_d[row*C_ + i], m = g_m[row*C_ + i];
        gx[r][i] = expf(-fmaxf(d*g_diag[i] + bgx[i], 0.f));
        ms[r][i] = m;
        __syncthreads();
        float acc2 = bcomb[i];
        #pragma unroll 8
        for (int j = 0; j < C_; j++) acc2 += gx[r][j] * g_WcT[j*C_ + i];
        #pragma unroll 8
        for (int j = 0; j < C_; j++) acc2 += ms[r][j] * g_WcT[(C_ + j)*C_ + i];
        g_al[row*C_ + i] = acc2;
        __syncthreads();
    }
}

// ======================= persistent sequential kernel (512 threads) =======================
#define SW_OFF   0
#define SW_SZ    (K_*68)                 // 43520
#define AS_OFF   (SW_OFF + SW_SZ)        // A staging [2][32][66]
#define AS_SZ    (2*32*66)               // 4224
#define HD_OFF   (AS_OFF + AS_SZ)        // 1024
#define PART_OFF (HD_OFF + 2*H_)         // 512
#define XH_OFF   (PART_OFF + 512)
#define XC_OFF   (XH_OFF + 2*C_)
#define MS_OFF   (XC_OFF + 2*C_)
#define VS_OFF   (MS_OFF + 2*C_)
#define SMEM_FLOATS (VS_OFF + 2*C_)      // 49792 floats = 199168 B

__global__ void __launch_bounds__(NTHR, 1) k_seq(const float* __restrict__ bhist,
                                                 const float* __restrict__ bfeat,
                                                 float* __restrict__ out) {
    extern __shared__ __align__(16) float sm[];
    float* Wsm  = sm + SW_OFF;
    float* As   = sm + AS_OFF;
    float* hd   = sm + HD_OFF;
    float* part = sm + PART_OFF;
    float* xh   = sm + XH_OFF;
    float* xc   = sm + XC_OFF;
    float* msh  = sm + MS_OFF;
    float* vsh  = sm + VS_OFF;

    int tid = threadIdx.x, blk = blockIdx.x;
    int m0 = (blk & 3) << 6, n0 = (blk >> 2) << 6;
    int tx = tid & 31;          // 2 m-rows: m0 + tx*2 + {0,1}
    int ty = tid >> 5;          // warp id 0..15: 4 n-cols n0 + ty*4 + {0..3}
    int mm = tid >> 3, kk4 = (tid & 7) << 2;   // staging map: 64 rows x 8 k-quads
    int b0 = blk * 2;

    for (int i = tid; i < 64*K_; i += NTHR) {
        int nl = i / K_, k = i - nl*K_;
        Wsm[k*68 + nl] = g_Wcat[(n0 + nl)*K_ + k];
    }
    float4 bq = *(const float4*)&g_bias[n0 + ty*4];
    int u_ep = (n0 + ty*4) >> 2;
    float cst[2] = {0.f, 0.f};
    __syncthreads();

    // staging: h-part chunks (k<512) computed on the fly from g_h * g_gh
    #define STAGE_H(buf, kc, tB) { \
        float4 h0 = *(const float4*)&g_h[(m0+mm)*H_ + (kc) + kk4]; \
        float4 q0 = *(const float4*)&g_gh[((tB) + m0 + mm)*H_ + (kc) + kk4]; \
        float* Ab = As + (buf)*(32*66); \
        Ab[(kk4+0)*66+mm]=h0.x*q0.x; Ab[(kk4+1)*66+mm]=h0.y*q0.y; \
        Ab[(kk4+2)*66+mm]=h0.z*q0.z; Ab[(kk4+3)*66+mm]=h0.w*q0.w; }

    // staging: c_c|m chunks (k>=512) from compact g_A
    #define STAGE_C(buf, kcl) { \
        float4 a0 = *(const float4*)&g_A[(m0+mm)*128 + (kcl) + kk4]; \
        float* Ab = As + (buf)*(32*66); \
        Ab[(kk4+0)*66+mm]=a0.x; Ab[(kk4+1)*66+mm]=a0.y; \
        Ab[(kk4+2)*66+mm]=a0.z; Ab[(kk4+3)*66+mm]=a0.w; }

    #define INNER(buf, Wb) { \
        const float* Ab = As + (buf)*(32*66); \
        _Pragma("unroll") \
        for (int kk = 0; kk < 32; kk++) { \
            float2 a = *(const float2*)&Ab[kk*66 + tx*2]; \
            ulonglong2 w = *(const ulonglong2*)&(Wb)[kk*68 + ty*4]; \
            unsigned long long a0 = dup2(a.x), a1 = dup2(a.y); \
            ffma2(acc[0][0], a0, w.x); ffma2(acc[0][1], a0, w.y); \
            ffma2(acc[1][0], a1, w.x); ffma2(acc[1][1], a1, w.y); \
        } }

    for (int t = 0; t < T_; t++) {
        int tB = t * B_;
        // prefetch GEMM chunk 0 (depends only on g_h)
        STAGE_H(0, 0, tB);

        // ---------------- phase A (local rows b0, b0+1) ----------------
        if (tid < 128) {
            int r = tid >> 6, c = tid & 63;
            int o = (tB + b0 + r)*C_ + c;
            msh[tid] = g_m[o]; vsh[tid] = g_v[o];
        }
        if (tid < 256) {
            int r = tid >> 7, u0 = (tid & 127) * 4;
            int b = b0 + r;
            float4 h4 = *(const float4*)&g_h[b*H_ + u0];
            float4 gh4 = *(const float4*)&g_gh[(tB + b)*H_ + u0];
            float4 v = make_float4(h4.x*gh4.x, h4.y*gh4.y, h4.z*gh4.z, h4.w*gh4.w);
            *(float4*)&hd[r*H_ + u0] = v;
        }
        __syncthreads();
        {   // x_h GEMV: 2 rows x 4 u-quarters x 64 c = 512 threads
            int r = tid >> 8, q = (tid >> 6) & 3, c = tid & 63;
            const float* hp = &hd[r*H_ + q*128];
            const float* wp = &g_WhT[(q*128)*C_ + c];
            float a0 = 0.f, a1 = 0.f, a2 = 0.f, a3 = 0.f;
            #pragma unroll 8
            for (int u = 0; u < 128; u += 4) {
                a0 += hp[u+0] * wp[(u+0)*C_];
                a1 += hp[u+1] * wp[(u+1)*C_];
                a2 += hp[u+2] * wp[(u+2)*C_];
                a3 += hp[u+3] * wp[(u+3)*C_];
            }
            part[tid] = (a0 + a1) + (a2 + a3);
        }
        __syncthreads();
        if (tid < 128) {
            int r = tid >> 6, c = tid & 63;
            float x_h = part[r*256 + c] + part[r*256 + 64 + c]
                      + part[r*256 + 128 + c] + part[r*256 + 192 + c] + bhist[c];
            xh[tid] = x_h;
            float m = msh[tid], v = vsh[tid];
            xc[tid] = m*v + (1.f - m)*x_h;
        }
        __syncthreads();
        if (tid < 128) {
            int r = tid >> 6, i = tid & 63;
            int b = b0 + r;
            float z = bfeat[i];
            const float* xp = &xc[r*C_];
            #pragma unroll 8
            for (int j = 0; j < C_; j++) z += xp[j] * g_WfT[j*C_ + i];
            float al = g_al[(tB + b)*C_ + i];
            float x_h = xh[tid];
            float ch = al*z + (1.f - al)*x_h;
            float m = msh[tid], v = vsh[tid];
            float cc = m*v + (1.f - m)*ch;
            out[(b*T_ + t)*C_ + i] = cc;
            g_A[b*128 + i] = cc;
            g_A[b*128 + 64 + i] = m;
        }
        __syncthreads();   // As buf0 complete for all threads

        // ---------------- GEMM h-part: 16 chunks ----------------
        unsigned long long acc[2][2] = {};
        for (int ch = 0; ch < 16; ch++) {
            int buf = ch & 1;
            if (ch < 15) STAGE_H(buf ^ 1, (ch + 1) * 32, tB);
            INNER(buf, Wsm + (ch*32)*68);
            __syncthreads();
        }

        gbar();   // all blocks' c_c|m published

        // ---------------- GEMM c_c|m part: 4 chunks ----------------
        STAGE_C(0, 0);
        __syncthreads();
        for (int ch = 0; ch < 4; ch++) {
            int buf = ch & 1;
            if (ch < 3) STAGE_C(buf ^ 1, (ch + 1) * 32);
            INNER(buf, Wsm + ((16 + ch)*32)*68);
            __syncthreads();
        }

        // ---------------- LSTM epilogue: 2 rows x 1 unit per thread ----------------
        #pragma unroll
        for (int mi = 0; mi < 2; mi++) {
            int b = m0 + tx*2 + mi;
            float2 p0 = upk2(acc[mi][0]), p1 = upk2(acc[mi][1]);
            float gi = p0.x + bq.x;
            float gf = p0.y + bq.y;
            float gg = p1.x + bq.z;
            float go = p1.y + bq.w;
            float co = cst[mi];
            float si = 1.f/(1.f + expf(-gi));
            float sf = 1.f/(1.f + expf(-gf));
            float so = 1.f/(1.f + expf(-go));
            float cn = sf*co + si*tanhf(gg);
            cst[mi] = cn;
            g_h[b*H_ + u_ep] = so*tanhf(cn);
        }
        gbar();   // g_h complete chip-wide
    }
    #undef STAGE_H
    #undef STAGE_C
    #undef INNER
}

extern "C" void kernel_launch(void* const* d_in, const int* in_sizes, int n_in,
                              void* d_out, int out_size) {
    const float* data  = (const float*)d_in[0];
    const float* Wih   = (const float*)d_in[1];
    const float* Whh   = (const float*)d_in[2];
    const float* bih   = (const float*)d_in[3];
    const float* bhh   = (const float*)d_in[4];
    const float* Wgh   = (const float*)d_in[5];
    const float* bgh   = (const float*)d_in[6];
    const float* Wgx   = (const float*)d_in[7];
    const float* bgx   = (const float*)d_in[8];
    const float* Whist = (const float*)d_in[9];
    const float* bhist = (const float*)d_in[10];
    const float* Wfeat = (const float*)d_in[11];
    const float* bfeat = (const float*)d_in[12];
    const float* Wcomb = (const float*)d_in[13];
    const float* bcomb = (const float*)d_in[14];
    float* out = (float*)d_out;

    static int smem_set = 0;
    if (!smem_set) {
        cudaFuncSetAttribute(k_seq, cudaFuncAttributeMaxDynamicSharedMemorySize,
                             SMEM_FLOATS * sizeof(float));
        smem_set = 1;
    }

    k_pack<<<2048, 256>>>(Wih, Whh, Whist, Wfeat, Wcomb, bih, bhh, Wgx);   // #1
    k_prep<<<64, 256>>>(data);                                             // #2
    k_ga<<<8192, 256>>>(Wgh, bgh, bgx, bcomb);                             // #3
    k_seq<<<NBLK, NTHR, SMEM_FLOATS * sizeof(float)>>>(bhist, bfeat, out); // #4 (profiled slot)
}

// round 14
// speedup vs baseline: 1.2502x; 1.2502x over previous
#include <cuda_runtime.h>
#include <math.h>

#define T_ 256
#define B_ 256
#define C_ 64
#define H_ 512
#define G_ 2048
#define K_ 640   // 512 (h) + 64 (c_c) + 64 (m)
#define NBLK 128

// ---- static device scratch ----
__device__ float g_v[T_*B_*C_];
__device__ float g_m[T_*B_*C_];
__device__ float g_d[T_*B_*C_];
__device__ float g_gh[T_*B_*H_];    // gamma_h (134MB)
__device__ float g_al[T_*B_*C_];
__device__ float g_A[B_*128];       // [c_c | m] (h part staged from g_h*g_gh)
__device__ float g_h[B_*H_];
__device__ float g_Wcat[G_*K_];     // [u*4+gate][k]
__device__ float g_bias[G_];
__device__ float g_WhT[H_*C_];
__device__ float g_WfT[C_*C_];
__device__ float g_WcT[2*C_*C_];
__device__ float g_diag[C_];
__device__ unsigned g_arrive;
__device__ unsigned g_gen;

// ---- f32x2 packed FMA helpers ----
__device__ __forceinline__ unsigned long long dup2(float a) {
    unsigned long long r;
    asm("mov.b64 %0, {%1,%1};" : "=l"(r) : "f"(a));
    return r;
}
__device__ __forceinline__ void ffma2(unsigned long long& d, unsigned long long a,
                                      unsigned long long b) {
    asm("fma.rn.f32x2 %0, %1, %2, %0;" : "+l"(d) : "l"(a), "l"(b));
}
__device__ __forceinline__ float2 upk2(unsigned long long v) {
    float2 f;
    asm("mov.b64 {%0,%1}, %2;" : "=f"(f.x), "=f"(f.y) : "l"(v));
    return f;
}

// ---- grid barrier (tight acquire-load poll, no nanosleep) ----
__device__ __forceinline__ void gbar() {
    __threadfence();
    __syncthreads();
    if (threadIdx.x == 0) {
        unsigned gen;
        asm volatile("ld.acquire.gpu.global.u32 %0, [%1];" : "=r"(gen) : "l"(&g_gen));
        unsigned a = atomicAdd(&g_arrive, 1u);
        if (a == NBLK - 1) {
            atomicExch(&g_arrive, 0u);
            __threadfence();
            atomicAdd(&g_gen, 1u);
        } else {
            unsigned g;
            do {
                asm volatile("ld.acquire.gpu.global.u32 %0, [%1];" : "=r"(g) : "l"(&g_gen));
            } while (g == gen);
        }
    }
    __syncthreads();
}

// ======================= preamble kernels (3 launches) =======================

__global__ void k_pack(const float* __restrict__ Wih,   const float* __restrict__ Whh,
                       const float* __restrict__ Whist, const float* __restrict__ Wfeat,
                       const float* __restrict__ Wcomb, const float* __restrict__ bih,
                       const float* __restrict__ bhh,   const float* __restrict__ Wgx) {
    int tid = blockIdx.x*blockDim.x + threadIdx.x, n = gridDim.x*blockDim.x;
    for (int i = tid; i < G_*K_; i += n) {
        int gp = i / K_, k = i % K_;
        int u = gp >> 2, gate = gp & 3;
        int go = gate*H_ + u;
        float w;
        if (k < H_)            w = Whh[go*H_ + k];
        else if (k < H_ + C_)  w = Wih[go*2*C_ + (k - H_)];
        else                   w = Wih[go*2*C_ + C_ + (k - H_ - C_)];
        g_Wcat[i] = w;
    }
    for (int i = tid; i < H_*C_; i += n) { int u=i/C_, c=i%C_; g_WhT[i] = Whist[c*H_ + u]; }
    for (int i = tid; i < C_*C_; i += n) { int j=i/C_, c=i%C_; g_WfT[i] = (j==c)?0.f:Wfeat[c*C_ + j]; }
    for (int i = tid; i < 2*C_*C_; i += n) { int j=i/C_, c=i%C_; g_WcT[i] = Wcomb[c*2*C_ + j]; }
    for (int i = tid; i < C_; i += n) g_diag[i] = Wgx[i*C_ + i];
    for (int i = tid; i < G_; i += n) { int u=i>>2, g=i&3; int go=g*H_+u; g_bias[i] = bih[go] + bhh[go]; }
    for (int i = tid; i < B_*H_; i += n) g_h[i] = 0.f;
}

__global__ void k_prep(const float* __restrict__ data) {
    int id = blockIdx.x*blockDim.x + threadIdx.x;
    if (id >= B_*C_) return;
    int b = id / C_, c = id % C_;
    float dec = 1.f, m_prev = 1.f;
    for (int t = 0; t < T_; t++) {
        float x = data[(b*T_ + t)*C_ + c];
        float m = (x != x) ? 0.f : 1.f;
        float v = (x != x) ? 0.f : x;
        float del;
        if (t == 0) del = 0.f;
        else if (t == 1) del = 1.f;
        else { dec = (m_prev == 1.f) ? 1.f : dec + 1.f; del = dec; }
        int o = (t*B_ + b)*C_ + c;
        g_v[o] = v; g_m[o] = m; g_d[o] = del;
        m_prev = m;
    }
}

__global__ void __launch_bounds__(256) k_ga(const float* __restrict__ Wgh,
                                            const float* __restrict__ bgh,
                                            const float* __restrict__ bgx,
                                            const float* __restrict__ bcomb) {
    __shared__ __align__(16) float As[2][32][68];
    __shared__ __align__(16) float Ws[2][32][68];
    __shared__ float gx[4][C_], ms[4][C_];
    int m0 = (blockIdx.x >> 3) << 6;
    int n0 = (blockIdx.x & 7) << 6;
    int tid = threadIdx.x, tx = tid & 15, ty = tid >> 4;
    int mm = tid >> 3, kk4 = (tid & 7) << 2;

    unsigned long long acc[4][2] = {};
    #define STAGE_G(buf, kc) { \
        float4 a0 = *(const float4*)&g_d[(m0+mm)*C_ + (kc) + kk4]; \
        float4 a1 = *(const float4*)&g_d[(m0+mm+32)*C_ + (kc) + kk4]; \
        float4 w0 = *(const float4*)&Wgh[(n0+mm)*C_ + (kc) + kk4]; \
        float4 w1 = *(const float4*)&Wgh[(n0+mm+32)*C_ + (kc) + kk4]; \
        As[buf][kk4+0][mm]=a0.x; As[buf][kk4+1][mm]=a0.y; As[buf][kk4+2][mm]=a0.z; As[buf][kk4+3][mm]=a0.w; \
        As[buf][kk4+0][mm+32]=a1.x; As[buf][kk4+1][mm+32]=a1.y; As[buf][kk4+2][mm+32]=a1.z; As[buf][kk4+3][mm+32]=a1.w; \
        Ws[buf][kk4+0][mm]=w0.x; Ws[buf][kk4+1][mm]=w0.y; Ws[buf][kk4+2][mm]=w0.z; Ws[buf][kk4+3][mm]=w0.w; \
        Ws[buf][kk4+0][mm+32]=w1.x; Ws[buf][kk4+1][mm+32]=w1.y; Ws[buf][kk4+2][mm+32]=w1.z; Ws[buf][kk4+3][mm+32]=w1.w; }

    STAGE_G(0, 0);
    __syncthreads();
    #pragma unroll
    for (int ch = 0; ch < 2; ch++) {
        int buf = ch & 1;
        if (ch < 1) STAGE_G(1, 32);
        #pragma unroll
        for (int kk = 0; kk < 32; kk++) {
            float4 a = *(const float4*)&As[buf][kk][tx*4];
            ulonglong2 w = *(const ulonglong2*)&Ws[buf][kk][ty*4];
            unsigned long long a0 = dup2(a.x), a1 = dup2(a.y), a2 = dup2(a.z), a3 = dup2(a.w);
            ffma2(acc[0][0], a0, w.x); ffma2(acc[0][1], a0, w.y);
            ffma2(acc[1][0], a1, w.x); ffma2(acc[1][1], a1, w.y);
            ffma2(acc[2][0], a2, w.x); ffma2(acc[2][1], a2, w.y);
            ffma2(acc[3][0], a3, w.x); ffma2(acc[3][1], a3, w.y);
        }
        __syncthreads();
    }
    int u0 = n0 + ty*4;
    float4 b4 = *(const float4*)&bgh[u0];
    #pragma unroll
    for (int mi = 0; mi < 4; mi++) {
        int row = m0 + tx*4 + mi;
        float2 p0 = upk2(acc[mi][0]), p1 = upk2(acc[mi][1]);
        float4 v;
        v.x = expf(-fmaxf(p0.x + b4.x, 0.f));
        v.y = expf(-fmaxf(p0.y + b4.y, 0.f));
        v.z = expf(-fmaxf(p1.x + b4.z, 0.f));
        v.w = expf(-fmaxf(p1.y + b4.w, 0.f));
        *(float4*)&g_gh[row*H_ + u0] = v;
    }
    #undef STAGE_G

    __syncthreads();
    int row0 = blockIdx.x * 8;
    int r = tid >> 6, i = tid & 63;
    for (int p = 0; p < 2; p++) {
        int row = row0 + p*4 + r;
        float d = g_d[row*C_ + i], m = g_m[row*C_ + i];
        gx[r][i] = expf(-fmaxf(d*g_diag[i] + bgx[i], 0.f));
        ms[r][i] = m;
        __syncthreads();
        float acc2 = bcomb[i];
        #pragma unroll 8
        for (int j = 0; j < C_; j++) acc2 += gx[r][j] * g_WcT[j*C_ + i];
        #pragma unroll 8
        for (int j = 0; j < C_; j++) acc2 += ms[r][j] * g_WcT[(C_ + j)*C_ + i];
        g_al[row*C_ + i] = acc2;
        __syncthreads();
    }
}

// ======================= persistent sequential kernel =======================
// 256 threads. 4-deep smem A-ring + register prefetch (2 chunks in flight).
#define SW_OFF   0
#define SW_SZ    (K_*68)                 // 43520
#define AS_OFF   (SW_OFF + SW_SZ)        // A staging ring [4][32][68]
#define AS_SZ    (4*32*68)               // 8704
#define HD_OFF   (AS_OFF + AS_SZ)
#define PART_OFF (HD_OFF + 2*H_)
#define XH_OFF   (PART_OFF + 256)
#define XC_OFF   (XH_OFF + 2*C_)
#define MS_OFF   (XC_OFF + 2*C_)
#define VS_OFF   (MS_OFF + 2*C_)
#define SMEM_FLOATS (VS_OFF + 2*C_)      // 54016 floats = 216064 B

__global__ void __launch_bounds__(256, 1) k_seq(const float* __restrict__ bhist,
                                                const float* __restrict__ bfeat,
                                                float* __restrict__ out) {
    extern __shared__ __align__(16) float sm[];
    float* Wsm  = sm + SW_OFF;
    float* As   = sm + AS_OFF;
    float* hd   = sm + HD_OFF;
    float* part = sm + PART_OFF;
    float* xh   = sm + XH_OFF;
    float* xc   = sm + XC_OFF;
    float* msh  = sm + MS_OFF;
    float* vsh  = sm + VS_OFF;

    int tid = threadIdx.x, blk = blockIdx.x;
    int m0 = (blk & 3) << 6, n0 = (blk >> 2) << 6;
    int tx = tid & 15, ty = tid >> 4;
    int mm = tid >> 3, kk4 = (tid & 7) << 2;
    int b0 = blk * 2;

    for (int i = tid; i < 64*K_; i += 256) {
        int nl = i / K_, k = i - nl*K_;
        Wsm[k*68 + nl] = g_Wcat[(n0 + nl)*K_ + k];
    }
    float4 bq = *(const float4*)&g_bias[n0 + ty*4];
    int u_ep = (n0 + ty*4) >> 2;
    float cst[4] = {0.f, 0.f, 0.f, 0.f};
    __syncthreads();

    // register-held chunk loads (h part): 4 float4 each
    float4 Ah0, Aq0, Ah1, Aq1;
    float4 Bh0, Bq0, Bh1, Bq1;

    #define LDGH_A(kc, tB) { \
        Ah0 = *(const float4*)&g_h[(m0+mm)*H_ + (kc) + kk4]; \
        Aq0 = *(const float4*)&g_gh[((tB) + m0 + mm)*H_ + (kc) + kk4]; \
        Ah1 = *(const float4*)&g_h[(m0+mm+32)*H_ + (kc) + kk4]; \
        Aq1 = *(const float4*)&g_gh[((tB) + m0 + mm + 32)*H_ + (kc) + kk4]; }
    #define LDGH_B(kc, tB) { \
        Bh0 = *(const float4*)&g_h[(m0+mm)*H_ + (kc) + kk4]; \
        Bq0 = *(const float4*)&g_gh[((tB) + m0 + mm)*H_ + (kc) + kk4]; \
        Bh1 = *(const float4*)&g_h[(m0+mm+32)*H_ + (kc) + kk4]; \
        Bq1 = *(const float4*)&g_gh[((tB) + m0 + mm + 32)*H_ + (kc) + kk4]; }
    #define STSH_A(buf) { float* Ab = As + (buf)*(32*68); \
        Ab[(kk4+0)*68+mm]=Ah0.x*Aq0.x; Ab[(kk4+1)*68+mm]=Ah0.y*Aq0.y; \
        Ab[(kk4+2)*68+mm]=Ah0.z*Aq0.z; Ab[(kk4+3)*68+mm]=Ah0.w*Aq0.w; \
        Ab[(kk4+0)*68+mm+32]=Ah1.x*Aq1.x; Ab[(kk4+1)*68+mm+32]=Ah1.y*Aq1.y; \
        Ab[(kk4+2)*68+mm+32]=Ah1.z*Aq1.z; Ab[(kk4+3)*68+mm+32]=Ah1.w*Aq1.w; }
    #define STSH_B(buf) { float* Ab = As + (buf)*(32*68); \
        Ab[(kk4+0)*68+mm]=Bh0.x*Bq0.x; Ab[(kk4+1)*68+mm]=Bh0.y*Bq0.y; \
        Ab[(kk4+2)*68+mm]=Bh0.z*Bq0.z; Ab[(kk4+3)*68+mm]=Bh0.w*Bq0.w; \
        Ab[(kk4+0)*68+mm+32]=Bh1.x*Bq1.x; Ab[(kk4+1)*68+mm+32]=Bh1.y*Bq1.y; \
        Ab[(kk4+2)*68+mm+32]=Bh1.z*Bq1.z; Ab[(kk4+3)*68+mm+32]=Bh1.w*Bq1.w; }

    #define STAGE_C(buf, kcl) { \
        float4 a0 = *(const float4*)&g_A[(m0+mm)*128 + (kcl) + kk4]; \
        float4 a1 = *(const float4*)&g_A[(m0+mm+32)*128 + (kcl) + kk4]; \
        float* Ab = As + (buf)*(32*68); \
        Ab[(kk4+0)*68+mm]=a0.x; Ab[(kk4+1)*68+mm]=a0.y; Ab[(kk4+2)*68+mm]=a0.z; Ab[(kk4+3)*68+mm]=a0.w; \
        Ab[(kk4+0)*68+mm+32]=a1.x; Ab[(kk4+1)*68+mm+32]=a1.y; Ab[(kk4+2)*68+mm+32]=a1.z; Ab[(kk4+3)*68+mm+32]=a1.w; }

    #define INNER(buf, Wb) { \
        const float* Ab = As + (buf)*(32*68); \
        _Pragma("unroll") \
        for (int kk = 0; kk < 32; kk++) { \
            float4 a = *(const float4*)&Ab[kk*68 + tx*4]; \
            ulonglong2 w = *(const ulonglong2*)&(Wb)[kk*68 + ty*4]; \
            unsigned long long a0 = dup2(a.x), a1 = dup2(a.y), a2 = dup2(a.z), a3 = dup2(a.w); \
            ffma2(acc[0][0], a0, w.x); ffma2(acc[0][1], a0, w.y); \
            ffma2(acc[1][0], a1, w.x); ffma2(acc[1][1], a1, w.y); \
            ffma2(acc[2][0], a2, w.x); ffma2(acc[2][1], a2, w.y); \
            ffma2(acc[3][0], a3, w.x); ffma2(acc[3][1], a3, w.y); \
        } }

    for (int t = 0; t < T_; t++) {
        int tB = t * B_;
        // issue chunk 0,1 loads now — they complete during phase A
        LDGH_A(0, tB);
        LDGH_B(32, tB);

        // ---------------- phase A (local rows b0, b0+1) ----------------
        if (tid < 128) {
            int r = tid >> 6, c = tid & 63;
            int o = (tB + b0 + r)*C_ + c;
            msh[tid] = g_m[o]; vsh[tid] = g_v[o];
        }
        {
            int r = tid >> 7, u0 = (tid & 127) * 4;
            int b = b0 + r;
            float4 h4 = *(const float4*)&g_h[b*H_ + u0];
            float4 gh4 = *(const float4*)&g_gh[(tB + b)*H_ + u0];
            float4 v = make_float4(h4.x*gh4.x, h4.y*gh4.y, h4.z*gh4.z, h4.w*gh4.w);
            *(float4*)&hd[r*H_ + u0] = v;
        }
        __syncthreads();
        {
            int r = tid >> 7, half = (tid >> 6) & 1, c = tid & 63;
            const float* hp = &hd[r*H_ + half*256];
            const float* wp = &g_WhT[(half*256)*C_ + c];
            float a0 = 0.f, a1 = 0.f, a2 = 0.f, a3 = 0.f;
            #pragma unroll 8
            for (int u = 0; u < 256; u += 4) {
                a0 += hp[u+0] * wp[(u+0)*C_];
                a1 += hp[u+1] * wp[(u+1)*C_];
                a2 += hp[u+2] * wp[(u+2)*C_];
                a3 += hp[u+3] * wp[(u+3)*C_];
            }
            part[tid] = (a0 + a1) + (a2 + a3);
        }
        __syncthreads();
        if (tid < 128) {
            int r = tid >> 6, c = tid & 63;
            float x_h = part[r*128 + c] + part[r*128 + 64 + c] + bhist[c];
            xh[tid] = x_h;
            float m = msh[tid], v = vsh[tid];
            xc[tid] = m*v + (1.f - m)*x_h;
        }
        __syncthreads();
        if (tid < 128) {
            int r = tid >> 6, i = tid & 63;
            int b = b0 + r;
            float z = bfeat[i];
            const float* xp = &xc[r*C_];
            #pragma unroll 8
            for (int j = 0; j < C_; j++) z += xp[j] * g_WfT[j*C_ + i];
            float al = g_al[(tB + b)*C_ + i];
            float x_h = xh[tid];
            float ch = al*z + (1.f - al)*x_h;
            float m = msh[tid], v = vsh[tid];
            float cc = m*v + (1.f - m)*ch;
            out[(b*T_ + t)*C_ + i] = cc;
            g_A[b*128 + i] = cc;
            g_A[b*128 + 64 + i] = m;
        }

        // fill ring bufs 0,1 from regs; refill regs with chunks 2,3
        STSH_A(0); LDGH_A(2*32, tB);
        STSH_B(1); LDGH_B(3*32, tB);
        __syncthreads();

        // ---------------- GEMM h-part: 16 chunks, pipelined ----------------
        unsigned long long acc[4][2] = {};
        #pragma unroll 4
        for (int ch = 0; ch < 16; ch++) {
            INNER(ch & 3, Wsm + (ch*32)*68);
            int nc = ch + 2;
            if (nc < 16) {
                if (ch & 1) { STSH_B(nc & 3); if (nc + 2 < 16) LDGH_B((nc+2)*32, tB); }
                else        { STSH_A(nc & 3); if (nc + 2 < 16) LDGH_A((nc+2)*32, tB); }
            }
            __syncthreads();
        }

        gbar();   // all blocks' c_c|m published

        // ---------------- GEMM c_c|m part: 4 chunks (L2-hot, depth-1) ----------------
        STAGE_C(0, 0);
        __syncthreads();
        for (int ch = 0; ch < 4; ch++) {
            int buf = ch & 1;
            if (ch < 3) STAGE_C(buf ^ 1, (ch + 1) * 32);
            INNER(buf, Wsm + ((16 + ch)*32)*68);
            __syncthreads();
        }

        // ---------------- LSTM epilogue ----------------
        #pragma unroll
        for (int mi = 0; mi < 4; mi++) {
            int b = m0 + tx*4 + mi;
            float2 p0 = upk2(acc[mi][0]), p1 = upk2(acc[mi][1]);
            float gi = p0.x + bq.x;
            float gf = p0.y + bq.y;
            float gg = p1.x + bq.z;
            float go = p1.y + bq.w;
            float co = cst[mi];
            float si = 1.f/(1.f + expf(-gi));
            float sf = 1.f/(1.f + expf(-gf));
            float so = 1.f/(1.f + expf(-go));
            float cn = sf*co + si*tanhf(gg);
            cst[mi] = cn;
            g_h[b*H_ + u_ep] = so*tanhf(cn);
        }
        gbar();   // g_h complete chip-wide
    }
    #undef LDGH_A
    #undef LDGH_B
    #undef STSH_A
    #undef STSH_B
    #undef STAGE_C
    #undef INNER
}

extern "C" void kernel_launch(void* const* d_in, const int* in_sizes, int n_in,
                              void* d_out, int out_size) {
    const float* data  = (const float*)d_in[0];
    const float* Wih   = (const float*)d_in[1];
    const float* Whh   = (const float*)d_in[2];
    const float* bih   = (const float*)d_in[3];
    const float* bhh   = (const float*)d_in[4];
    const float* Wgh   = (const float*)d_in[5];
    const float* bgh   = (const float*)d_in[6];
    const float* Wgx   = (const float*)d_in[7];
    const float* bgx   = (const float*)d_in[8];
    const float* Whist = (const float*)d_in[9];
    const float* bhist = (const float*)d_in[10];
    const float* Wfeat = (const float*)d_in[11];
    const float* bfeat = (const float*)d_in[12];
    const float* Wcomb = (const float*)d_in[13];
    const float* bcomb = (const float*)d_in[14];
    float* out = (float*)d_out;

    static int smem_set = 0;
    if (!smem_set) {
        cudaFuncSetAttribute(k_seq, cudaFuncAttributeMaxDynamicSharedMemorySize,
                             SMEM_FLOATS * sizeof(float));
        smem_set = 1;
    }

    k_pack<<<2048, 256>>>(Wih, Whh, Whist, Wfeat, Wcomb, bih, bhh, Wgx);   // #1
    k_prep<<<64, 256>>>(data);                                             // #2
    k_ga<<<8192, 256>>>(Wgh, bgh, bgx, bcomb);                             // #3
    k_seq<<<NBLK, 256, SMEM_FLOATS * sizeof(float)>>>(bhist, bfeat, out);  // #4 (profiled slot)
}

// round 15
// speedup vs baseline: 1.4103x; 1.1281x over previous
#include <cuda_runtime.h>
#include <math.h>

#define T_ 256
#define B_ 256
#define C_ 64
#define H_ 512
#define G_ 2048
#define K_ 640   // 512 (h) + 64 (c_c) + 64 (m)
#define NBLK 128

// ---- static device scratch ----
__device__ float g_v[T_*B_*C_];
__device__ float g_m[T_*B_*C_];
__device__ float g_d[T_*B_*C_];
__device__ float g_gh[T_*B_*H_];    // gamma_h (134MB)
__device__ float g_al[T_*B_*C_];
__device__ float g_A[B_*128];       // [c_c | m]
__device__ float g_h[B_*H_];
__device__ float g_Wcat[G_*K_];     // [u*4+gate][k]
__device__ float g_bias[G_];
__device__ float g_WhT[H_*C_];
__device__ float g_WfT[C_*C_];
__device__ float g_WcT[2*C_*C_];
__device__ float g_diag[C_];
__device__ unsigned g_arrive;
__device__ unsigned g_gen;

// ---- f32x2 packed FMA helpers ----
__device__ __forceinline__ unsigned long long dup2(float a) {
    unsigned long long r;
    asm("mov.b64 %0, {%1,%1};" : "=l"(r) : "f"(a));
    return r;
}
__device__ __forceinline__ void ffma2(unsigned long long& d, unsigned long long a,
                                      unsigned long long b) {
    asm("fma.rn.f32x2 %0, %1, %2, %0;" : "+l"(d) : "l"(a), "l"(b));
}
__device__ __forceinline__ float2 upk2(unsigned long long v) {
    float2 f;
    asm("mov.b64 {%0,%1}, %2;" : "=f"(f.x), "=f"(f.y) : "l"(v));
    return f;
}

// group barriers (128 threads each)
#define BAR_WGA() asm volatile("bar.sync 1, 128;" ::: "memory")
#define BAR_WGB() asm volatile("bar.sync 2, 128;" ::: "memory")

// ---- grid barrier (all 256 threads; internal bar0 is the WGA/WGB join) ----
__device__ __forceinline__ void gbar() {
    __threadfence();
    __syncthreads();
    if (threadIdx.x == 0) {
        unsigned gen;
        asm volatile("ld.acquire.gpu.global.u32 %0, [%1];" : "=r"(gen) : "l"(&g_gen));
        unsigned a = atomicAdd(&g_arrive, 1u);
        if (a == NBLK - 1) {
            atomicExch(&g_arrive, 0u);
            __threadfence();
            atomicAdd(&g_gen, 1u);
        } else {
            unsigned g;
            do {
                asm volatile("ld.acquire.gpu.global.u32 %0, [%1];" : "=r"(g) : "l"(&g_gen));
            } while (g == gen);
        }
    }
    __syncthreads();
}

// ======================= preamble kernels (unchanged) =======================

__global__ void k_pack(const float* __restrict__ Wih,   const float* __restrict__ Whh,
                       const float* __restrict__ Whist, const float* __restrict__ Wfeat,
                       const float* __restrict__ Wcomb, const float* __restrict__ bih,
                       const float* __restrict__ bhh,   const float* __restrict__ Wgx) {
    int tid = blockIdx.x*blockDim.x + threadIdx.x, n = gridDim.x*blockDim.x;
    for (int i = tid; i < G_*K_; i += n) {
        int gp = i / K_, k = i % K_;
        int u = gp >> 2, gate = gp & 3;
        int go = gate*H_ + u;
        float w;
        if (k < H_)            w = Whh[go*H_ + k];
        else if (k < H_ + C_)  w = Wih[go*2*C_ + (k - H_)];
        else                   w = Wih[go*2*C_ + C_ + (k - H_ - C_)];
        g_Wcat[i] = w;
    }
    for (int i = tid; i < H_*C_; i += n) { int u=i/C_, c=i%C_; g_WhT[i] = Whist[c*H_ + u]; }
    for (int i = tid; i < C_*C_; i += n) { int j=i/C_, c=i%C_; g_WfT[i] = (j==c)?0.f:Wfeat[c*C_ + j]; }
    for (int i = tid; i < 2*C_*C_; i += n) { int j=i/C_, c=i%C_; g_WcT[i] = Wcomb[c*2*C_ + j]; }
    for (int i = tid; i < C_; i += n) g_diag[i] = Wgx[i*C_ + i];
    for (int i = tid; i < G_; i += n) { int u=i>>2, g=i&3; int go=g*H_+u; g_bias[i] = bih[go] + bhh[go]; }
    for (int i = tid; i < B_*H_; i += n) g_h[i] = 0.f;
}

__global__ void k_prep(const float* __restrict__ data) {
    int id = blockIdx.x*blockDim.x + threadIdx.x;
    if (id >= B_*C_) return;
    int b = id / C_, c = id % C_;
    float dec = 1.f, m_prev = 1.f;
    for (int t = 0; t < T_; t++) {
        float x = data[(b*T_ + t)*C_ + c];
        float m = (x != x) ? 0.f : 1.f;
        float v = (x != x) ? 0.f : x;
        float del;
        if (t == 0) del = 0.f;
        else if (t == 1) del = 1.f;
        else { dec = (m_prev == 1.f) ? 1.f : dec + 1.f; del = dec; }
        int o = (t*B_ + b)*C_ + c;
        g_v[o] = v; g_m[o] = m; g_d[o] = del;
        m_prev = m;
    }
}

__global__ void __launch_bounds__(256) k_ga(const float* __restrict__ Wgh,
                                            const float* __restrict__ bgh,
                                            const float* __restrict__ bgx,
                                            const float* __restrict__ bcomb) {
    __shared__ __align__(16) float As[2][32][68];
    __shared__ __align__(16) float Ws[2][32][68];
    __shared__ float gx[4][C_], ms[4][C_];
    int m0 = (blockIdx.x >> 3) << 6;
    int n0 = (blockIdx.x & 7) << 6;
    int tid = threadIdx.x, tx = tid & 15, ty = tid >> 4;
    int mm = tid >> 3, kk4 = (tid & 7) << 2;

    unsigned long long acc[4][2] = {};
    #define STAGE_G(buf, kc) { \
        float4 a0 = *(const float4*)&g_d[(m0+mm)*C_ + (kc) + kk4]; \
        float4 a1 = *(const float4*)&g_d[(m0+mm+32)*C_ + (kc) + kk4]; \
        float4 w0 = *(const float4*)&Wgh[(n0+mm)*C_ + (kc) + kk4]; \
        float4 w1 = *(const float4*)&Wgh[(n0+mm+32)*C_ + (kc) + kk4]; \
        As[buf][kk4+0][mm]=a0.x; As[buf][kk4+1][mm]=a0.y; As[buf][kk4+2][mm]=a0.z; As[buf][kk4+3][mm]=a0.w; \
        As[buf][kk4+0][mm+32]=a1.x; As[buf][kk4+1][mm+32]=a1.y; As[buf][kk4+2][mm+32]=a1.z; As[buf][kk4+3][mm+32]=a1.w; \
        Ws[buf][kk4+0][mm]=w0.x; Ws[buf][kk4+1][mm]=w0.y; Ws[buf][kk4+2][mm]=w0.z; Ws[buf][kk4+3][mm]=w0.w; \
        Ws[buf][kk4+0][mm+32]=w1.x; Ws[buf][kk4+1][mm+32]=w1.y; Ws[buf][kk4+2][mm+32]=w1.z; Ws[buf][kk4+3][mm+32]=w1.w; }

    STAGE_G(0, 0);
    __syncthreads();
    #pragma unroll
    for (int ch = 0; ch < 2; ch++) {
        int buf = ch & 1;
        if (ch < 1) STAGE_G(1, 32);
        #pragma unroll
        for (int kk = 0; kk < 32; kk++) {
            float4 a = *(const float4*)&As[buf][kk][tx*4];
            ulonglong2 w = *(const ulonglong2*)&Ws[buf][kk][ty*4];
            unsigned long long a0 = dup2(a.x), a1 = dup2(a.y), a2 = dup2(a.z), a3 = dup2(a.w);
            ffma2(acc[0][0], a0, w.x); ffma2(acc[0][1], a0, w.y);
            ffma2(acc[1][0], a1, w.x); ffma2(acc[1][1], a1, w.y);
            ffma2(acc[2][0], a2, w.x); ffma2(acc[2][1], a2, w.y);
            ffma2(acc[3][0], a3, w.x); ffma2(acc[3][1], a3, w.y);
        }
        __syncthreads();
    }
    int u0 = n0 + ty*4;
    float4 b4 = *(const float4*)&bgh[u0];
    #pragma unroll
    for (int mi = 0; mi < 4; mi++) {
        int row = m0 + tx*4 + mi;
        float2 p0 = upk2(acc[mi][0]), p1 = upk2(acc[mi][1]);
        float4 v;
        v.x = expf(-fmaxf(p0.x + b4.x, 0.f));
        v.y = expf(-fmaxf(p0.y + b4.y, 0.f));
        v.z = expf(-fmaxf(p1.x + b4.z, 0.f));
        v.w = expf(-fmaxf(p1.y + b4.w, 0.f));
        *(float4*)&g_gh[row*H_ + u0] = v;
    }
    #undef STAGE_G

    __syncthreads();
    int row0 = blockIdx.x * 8;
    int r = tid >> 6, i = tid & 63;
    for (int p = 0; p < 2; p++) {
        int row = row0 + p*4 + r;
        float d = g_d[row*C_ + i], m = g_m[row*C_ + i];
        gx[r][i] = expf(-fmaxf(d*g_diag[i] + bgx[i], 0.f));
        ms[r][i] = m;
        __syncthreads();
        float acc2 = bcomb[i];
        #pragma unroll 8
        for (int j = 0; j < C_; j++) acc2 += gx[r][j] * g_WcT[j*C_ + i];
        #pragma unroll 8
        for (int j = 0; j < C_; j++) acc2 += ms[r][j] * g_WcT[(C_ + j)*C_ + i];
        g_al[row*C_ + i] = acc2;
        __syncthreads();
    }
}

// ======================= persistent sequential kernel =======================
// Warp-specialized: warps 0-3 = phase A (2 rows), warps 4-7 = GEMM (64x64 tile).
#define SW_OFF   0
#define SW_SZ    (K_*68)                 // 43520
#define AS_OFF   (SW_OFF + SW_SZ)        // A ring [4][32][68]
#define AS_SZ    (4*32*68)               // 8704
#define HD_OFF   (AS_OFF + AS_SZ)        // 1024
#define XC_OFF   (HD_OFF + 2*H_)         // 128
#define SMEM_FLOATS (XC_OFF + 2*C_)      // 53376 floats = 213504 B

__global__ void __launch_bounds__(256, 1) k_seq(const float* __restrict__ bhist,
                                                const float* __restrict__ bfeat,
                                                float* __restrict__ out) {
    extern __shared__ __align__(16) float sm[];
    float* Wsm = sm + SW_OFF;
    float* As  = sm + AS_OFF;
    float* hd  = sm + HD_OFF;
    float* xc  = sm + XC_OFF;

    int tid = threadIdx.x, blk = blockIdx.x;
    int m0 = (blk & 3) << 6, n0 = (blk >> 2) << 6;
    int b0 = blk * 2;
    int tid2 = tid & 127;
    // WGB maps (harmless for WGA threads)
    int txB = tid2 & 15, tyB = tid2 >> 4;          // 4m x 8n micro-tile
    int mmB = tid2 >> 3, kkB = (tid2 & 7) << 2;    // staging: rows mmB+16s, kquad kkB
    // WGA maps
    int rA = tid2 >> 6, cA = tid2 & 63, bA = b0 + rA;

    for (int i = tid; i < 64*K_; i += 256) {
        int nl = i / K_, k = i - nl*K_;
        Wsm[k*68 + nl] = g_Wcat[(n0 + nl)*K_ + k];
    }
    float4 bqA = *(const float4*)&g_bias[n0 + tyB*8];
    float4 bqB = *(const float4*)&g_bias[n0 + tyB*8 + 4];
    int u_ep = (n0 + tyB*8) >> 2;                  // units u_ep, u_ep+1
    float cst[8] = {0.f,0.f,0.f,0.f,0.f,0.f,0.f,0.f};
    __syncthreads();

    // WGB register prefetch: 4 slots (rows mmB+16s) x {h,q} per set
    float4 Ph[4], Pq[4], Qh[4], Qq[4];

    #define LDGH_P(kc, tB) { _Pragma("unroll") for (int s = 0; s < 4; s++) { \
        Ph[s] = *(const float4*)&g_h[(m0+mmB+16*s)*H_ + (kc) + kkB]; \
        Pq[s] = *(const float4*)&g_gh[((tB)+m0+mmB+16*s)*H_ + (kc) + kkB]; } }
    #define LDGH_Q(kc, tB) { _Pragma("unroll") for (int s = 0; s < 4; s++) { \
        Qh[s] = *(const float4*)&g_h[(m0+mmB+16*s)*H_ + (kc) + kkB]; \
        Qq[s] = *(const float4*)&g_gh[((tB)+m0+mmB+16*s)*H_ + (kc) + kkB]; } }
    #define STSH_P(buf) { float* Ab = As + (buf)*(32*68); \
        _Pragma("unroll") for (int s = 0; s < 4; s++) { int rw = mmB + 16*s; \
            Ab[(kkB+0)*68+rw]=Ph[s].x*Pq[s].x; Ab[(kkB+1)*68+rw]=Ph[s].y*Pq[s].y; \
            Ab[(kkB+2)*68+rw]=Ph[s].z*Pq[s].z; Ab[(kkB+3)*68+rw]=Ph[s].w*Pq[s].w; } }
    #define STSH_Q(buf) { float* Ab = As + (buf)*(32*68); \
        _Pragma("unroll") for (int s = 0; s < 4; s++) { int rw = mmB + 16*s; \
            Ab[(kkB+0)*68+rw]=Qh[s].x*Qq[s].x; Ab[(kkB+1)*68+rw]=Qh[s].y*Qq[s].y; \
            Ab[(kkB+2)*68+rw]=Qh[s].z*Qq[s].z; Ab[(kkB+3)*68+rw]=Qh[s].w*Qq[s].w; } }
    #define STAGE_C(buf, kcl) { float* Ab = As + (buf)*(32*68); \
        _Pragma("unroll") for (int s = 0; s < 4; s++) { int rw = mmB + 16*s; \
            float4 a = *(const float4*)&g_A[(m0+rw)*128 + (kcl) + kkB]; \
            Ab[(kkB+0)*68+rw]=a.x; Ab[(kkB+1)*68+rw]=a.y; \
            Ab[(kkB+2)*68+rw]=a.z; Ab[(kkB+3)*68+rw]=a.w; } }

    #define INNER(buf, Wb) { \
        const float* Ab = As + (buf)*(32*68); \
        _Pragma("unroll") \
        for (int kk = 0; kk < 32; kk++) { \
            float4 a = *(const float4*)&Ab[kk*68 + txB*4]; \
            ulonglong2 w01 = *(const ulonglong2*)&(Wb)[kk*68 + tyB*8]; \
            ulonglong2 w23 = *(const ulonglong2*)&(Wb)[kk*68 + tyB*8 + 4]; \
            unsigned long long a0 = dup2(a.x), a1 = dup2(a.y), a2 = dup2(a.z), a3 = dup2(a.w); \
            ffma2(acc[0][0], a0, w01.x); ffma2(acc[0][1], a0, w01.y); \
            ffma2(acc[0][2], a0, w23.x); ffma2(acc[0][3], a0, w23.y); \
            ffma2(acc[1][0], a1, w01.x); ffma2(acc[1][1], a1, w01.y); \
            ffma2(acc[1][2], a1, w23.x); ffma2(acc[1][3], a1, w23.y); \
            ffma2(acc[2][0], a2, w01.x); ffma2(acc[2][1], a2, w01.y); \
            ffma2(acc[2][2], a2, w23.x); ffma2(acc[2][3], a2, w23.y); \
            ffma2(acc[3][0], a3, w01.x); ffma2(acc[3][1], a3, w01.y); \
            ffma2(acc[3][2], a3, w23.x); ffma2(acc[3][3], a3, w23.y); \
        } }

    for (int t = 0; t < T_; t++) {
        int tB = t * B_;
        unsigned long long acc[4][4] = {};

        if (tid < 128) {
            // ================= WGA: phase A for rows b0, b0+1 =================
            // hd: thread covers hd[rA*512 + cA*8 .. +7]
            {
                int u0 = cA * 8;
                float4 h4a = *(const float4*)&g_h[bA*H_ + u0];
                float4 q4a = *(const float4*)&g_gh[(tB + bA)*H_ + u0];
                float4 h4b = *(const float4*)&g_h[bA*H_ + u0 + 4];
                float4 q4b = *(const float4*)&g_gh[(tB + bA)*H_ + u0 + 4];
                *(float4*)&hd[rA*H_ + u0]     = make_float4(h4a.x*q4a.x, h4a.y*q4a.y, h4a.z*q4a.z, h4a.w*q4a.w);
                *(float4*)&hd[rA*H_ + u0 + 4] = make_float4(h4b.x*q4b.x, h4b.y*q4b.y, h4b.z*q4b.z, h4b.w*q4b.w);
            }
            float mv = g_m[(tB + bA)*C_ + cA];
            float vv = g_v[(tB + bA)*C_ + cA];
            BAR_WGA();
            // x_h GEMV: full 512-u chain, 8 acc for MLP
            float s0=0.f,s1=0.f,s2=0.f,s3=0.f,s4=0.f,s5=0.f,s6=0.f,s7=0.f;
            {
                const float* hp = &hd[rA*H_];
                const float* wp = &g_WhT[cA];
                #pragma unroll 8
                for (int u = 0; u < 512; u += 8) {
                    s0 += hp[u+0] * wp[(u+0)*C_];
                    s1 += hp[u+1] * wp[(u+1)*C_];
                    s2 += hp[u+2] * wp[(u+2)*C_];
                    s3 += hp[u+3] * wp[(u+3)*C_];
                    s4 += hp[u+4] * wp[(u+4)*C_];
                    s5 += hp[u+5] * wp[(u+5)*C_];
                    s6 += hp[u+6] * wp[(u+6)*C_];
                    s7 += hp[u+7] * wp[(u+7)*C_];
                }
            }
            float x_h = ((s0+s1)+(s2+s3)) + ((s4+s5)+(s6+s7)) + bhist[cA];
            float xcv = mv*vv + (1.f - mv)*x_h;
            xc[tid2] = xcv;
            BAR_WGA();
            // feat regression
            float z0=0.f,z1=0.f,z2=0.f,z3=0.f;
            {
                const float* xp = &xc[rA*C_];
                const float* fp = &g_WfT[cA];
                #pragma unroll 4
                for (int j = 0; j < C_; j += 4) {
                    z0 += xp[j+0] * fp[(j+0)*C_];
                    z1 += xp[j+1] * fp[(j+1)*C_];
                    z2 += xp[j+2] * fp[(j+2)*C_];
                    z3 += xp[j+3] * fp[(j+3)*C_];
                }
            }
            float z = (z0+z1) + (z2+z3) + bfeat[cA];
            float al = g_al[(tB + bA)*C_ + cA];
            float ch = al*z + (1.f - al)*x_h;
            float cc = mv*vv + (1.f - mv)*ch;
            out[(bA*T_ + t)*C_ + cA] = cc;
            g_A[bA*128 + cA] = cc;
            g_A[bA*128 + 64 + cA] = mv;
        } else {
            // ================= WGB: h-part GEMM (16 chunks) =================
            LDGH_P(0, tB);
            LDGH_Q(32, tB);
            STSH_P(0); LDGH_P(2*32, tB);
            STSH_Q(1); LDGH_Q(3*32, tB);
            BAR_WGB();
            #pragma unroll 4
            for (int ch = 0; ch < 16; ch++) {
                INNER(ch & 3, Wsm + (ch*32)*68);
                int nc = ch + 2;
                if (nc < 16) {
                    if (ch & 1) { STSH_Q(nc & 3); if (nc + 2 < 16) LDGH_Q((nc+2)*32, tB); }
                    else        { STSH_P(nc & 3); if (nc + 2 < 16) LDGH_P((nc+2)*32, tB); }
                }
                BAR_WGB();
            }
        }

        gbar();   // join + all blocks' c_c|m published

        if (tid >= 128) {
            // ================= WGB: c_c|m chunks + epilogue =================
            STAGE_C(0, 0);
            BAR_WGB();
            for (int ch = 0; ch < 4; ch++) {
                int buf = ch & 1;
                if (ch < 3) STAGE_C(buf ^ 1, (ch + 1) * 32);
                INNER(buf, Wsm + ((16 + ch)*32)*68);
                BAR_WGB();
            }
            #pragma unroll
            for (int mi = 0; mi < 4; mi++) {
                int b = m0 + txB*4 + mi;
                // unit u_ep: gates from acc[mi][0..1]
                float2 p0 = upk2(acc[mi][0]), p1 = upk2(acc[mi][1]);
                float gi = p0.x + bqA.x, gf = p0.y + bqA.y;
                float gg = p1.x + bqA.z, go = p1.y + bqA.w;
                float co = cst[mi*2];
                float si = 1.f/(1.f + expf(-gi));
                float sf = 1.f/(1.f + expf(-gf));
                float so = 1.f/(1.f + expf(-go));
                float cn = sf*co + si*tanhf(gg);
                cst[mi*2] = cn;
                g_h[b*H_ + u_ep] = so*tanhf(cn);
                // unit u_ep+1: gates from acc[mi][2..3]
                float2 p2 = upk2(acc[mi][2]), p3 = upk2(acc[mi][3]);
                float gi2 = p2.x + bqB.x, gf2 = p2.y + bqB.y;
                float gg2 = p3.x + bqB.z, go2 = p3.y + bqB.w;
                float co2 = cst[mi*2+1];
                float si2 = 1.f/(1.f + expf(-gi2));
                float sf2 = 1.f/(1.f + expf(-gf2));
                float so2 = 1.f/(1.f + expf(-go2));
                float cn2 = sf2*co2 + si2*tanhf(gg2);
                cst[mi*2+1] = cn2;
                g_h[b*H_ + u_ep + 1] = so2*tanhf(cn2);
            }
        }

        gbar();   // g_h complete chip-wide
    }
    #undef LDGH_P
    #undef LDGH_Q
    #undef STSH_P
    #undef STSH_Q
    #undef STAGE_C
    #undef INNER
}

extern "C" void kernel_launch(void* const* d_in, const int* in_sizes, int n_in,
                              void* d_out, int out_size) {
    const float* data  = (const float*)d_in[0];
    const float* Wih   = (const float*)d_in[1];
    const float* Whh   = (const float*)d_in[2];
    const float* bih   = (const float*)d_in[3];
    const float* bhh   = (const float*)d_in[4];
    const float* Wgh   = (const float*)d_in[5];
    const float* bgh   = (const float*)d_in[6];
    const float* Wgx   = (const float*)d_in[7];
    const float* bgx   = (const float*)d_in[8];
    const float* Whist = (const float*)d_in[9];
    const float* bhist = (const float*)d_in[10];
    const float* Wfeat = (const float*)d_in[11];
    const float* bfeat = (const float*)d_in[12];
    const float* Wcomb = (const float*)d_in[13];
    const float* bcomb = (const float*)d_in[14];
    float* out = (float*)d_out;

    static int smem_set = 0;
    if (!smem_set) {
        cudaFuncSetAttribute(k_seq, cudaFuncAttributeMaxDynamicSharedMemorySize,
                             SMEM_FLOATS * sizeof(float));
        smem_set = 1;
    }

    k_pack<<<2048, 256>>>(Wih, Whh, Whist, Wfeat, Wcomb, bih, bhh, Wgx);   // #1
    k_prep<<<64, 256>>>(data);                                             // #2
    k_ga<<<8192, 256>>>(Wgh, bgh, bgx, bcomb);                             // #3
    k_seq<<<NBLK, 256, SMEM_FLOATS * sizeof(float)>>>(bhist, bfeat, out);  // #4 (profiled slot)
}